// round 4
// baseline (speedup 1.0000x reference)
#include <cuda_runtime.h>
#include <cstdint>
#include <cstddef>

#define T_TOK 1024
#define HID   2048
#define IDIM  1024
#define NEXP  32
#define NGRP  8
#define EPG   4
#define TOPG  4
#define TOPK  8
#define NE    33      // 32 routed + 1 shared
#define CAP   1024
#define RSCALE 2.5f

// ---------------- static scratch (no allocations allowed) ----------------
__device__ float g_combine[T_TOK * NEXP];
__device__ int   g_count[NE];
__device__ int   g_token[NE * CAP];
__device__ float g_wt[NE * CAP];
__device__ int   g_rowid[NEXP * T_TOK];                    // [e][t] -> row or -1
__device__ float g_act[(size_t)NE * CAP * IDIM];           // silu(g)*u rows
__device__ float g_down[(size_t)NE * CAP * HID];           // weighted down-proj rows

// packed fp32x2 FMA (FFMA2 in SASS; 2x scalar FFMA throughput on sm_103a)
__device__ __forceinline__ float2 ffma2(float2 a, float2 b, float2 c) {
    float2 d;
    asm("fma.rn.f32x2 %0, %1, %2, %3;"
        : "=l"(*reinterpret_cast<unsigned long long*>(&d))
        : "l"(*reinterpret_cast<unsigned long long*>(&a)),
          "l"(*reinterpret_cast<unsigned long long*>(&b)),
          "l"(*reinterpret_cast<unsigned long long*>(&c)));
    return d;
}

__device__ __forceinline__ float silu_f(float v) {
    return v / (1.0f + expf(-v));
}

// ---------------- 1) router: logits -> sigmoid -> group-limited topk ----------------
__global__ void router_kernel(const float* __restrict__ x,
                              const float* __restrict__ gw,
                              const float* __restrict__ bias) {
    __shared__ float sx[HID];
    __shared__ float slog[NEXP];
    int t = blockIdx.x;
    const float* xr = x + (size_t)t * HID;
    for (int k = threadIdx.x; k < HID; k += blockDim.x) sx[k] = xr[k];
    __syncthreads();
    int warp = threadIdx.x >> 5, lane = threadIdx.x & 31;
    for (int e = warp; e < NEXP; e += 8) {
        const float* w = gw + (size_t)e * HID;
        float acc = 0.f;
        for (int k = lane; k < HID; k += 32) acc = fmaf(sx[k], w[k], acc);
        #pragma unroll
        for (int o = 16; o; o >>= 1) acc += __shfl_down_sync(0xffffffffu, acc, o);
        if (lane == 0) slog[e] = acc;
    }
    __syncthreads();
    if (threadIdx.x == 0) {
        float s[NEXP], sr[NEXP];
        #pragma unroll
        for (int e = 0; e < NEXP; e++) {
            float sc = 1.f / (1.f + expf(-slog[e]));
            s[e] = sc;
            sr[e] = sc + bias[e];
        }
        // group scores = sum of top-2 within group of 4
        float gs[NGRP];
        #pragma unroll
        for (int g = 0; g < NGRP; g++) {
            float m1 = -1e30f, m2 = -1e30f;
            #pragma unroll
            for (int j = 0; j < EPG; j++) {
                float v = sr[g * EPG + j];
                if (v > m1) { m2 = m1; m1 = v; }
                else if (v > m2) { m2 = v; }
            }
            gs[g] = m1 + m2;
        }
        // top-4 groups (strict > => lowest index on ties, matches jax top_k)
        bool gsel[NGRP];
        #pragma unroll
        for (int g = 0; g < NGRP; g++) gsel[g] = false;
        for (int it = 0; it < TOPG; it++) {
            float best = -1e30f; int bi = 0;
            for (int g = 0; g < NGRP; g++)
                if (!gsel[g] && gs[g] > best) { best = gs[g]; bi = g; }
            gsel[bi] = true;
        }
        // top-8 experts among selected groups
        bool taken[NEXP];
        #pragma unroll
        for (int e = 0; e < NEXP; e++) taken[e] = false;
        int ids[TOPK];
        for (int it = 0; it < TOPK; it++) {
            float best = -1e30f; int bi = 0;
            for (int e = 0; e < NEXP; e++)
                if (gsel[e >> 2] && !taken[e] && sr[e] > best) { best = sr[e]; bi = e; }
            taken[bi] = true;
            ids[it] = bi;
        }
        float sum = 0.f;
        for (int k = 0; k < TOPK; k++) sum += s[ids[k]];
        float inv = RSCALE / (sum + 1e-20f);
        float out[NEXP];
        #pragma unroll
        for (int e = 0; e < NEXP; e++) out[e] = 0.f;
        for (int k = 0; k < TOPK; k++) out[ids[k]] = s[ids[k]] * inv;
        #pragma unroll
        for (int e = 0; e < NEXP; e++) g_combine[t * NEXP + e] = out[e];
    }
}

// ---------------- 2) compact per-expert token lists (deterministic scan) ----------------
__global__ void build_lists_kernel() {
    int e = blockIdx.x;          // 0..32  (32 == shared expert)
    int t = threadIdx.x;         // 0..1023
    __shared__ int sc[T_TOK];
    float w;
    int flag;
    if (e < NEXP) {
        w = g_combine[t * NEXP + e];
        flag = (w > 0.f) ? 1 : 0;
    } else {
        w = 1.0f;
        flag = 1;
    }
    sc[t] = flag;
    __syncthreads();
    // Hillis-Steele inclusive scan
    for (int off = 1; off < T_TOK; off <<= 1) {
        int v = (t >= off) ? sc[t - off] : 0;
        __syncthreads();
        sc[t] += v;
        __syncthreads();
    }
    int pos = sc[t] - flag;
    if (flag) {
        g_token[e * CAP + pos] = t;
        g_wt[e * CAP + pos] = w;
    }
    if (e < NEXP) g_rowid[e * T_TOK + t] = flag ? (e * CAP + pos) : -1;
    if (t == T_TOK - 1) g_count[e] = sc[T_TOK - 1];
}

// ---------------- 3) gate_up GEMM + SiLU*u epilogue ----------------
// Block: 64 rows x 64 act-cols (computes g col n and u col n simultaneously).
__global__ void __launch_bounds__(256, 2)
gateup_kernel(const float* __restrict__ x,
              const float* __restrict__ wgu,
              const float* __restrict__ sgu) {
    int e = blockIdx.z;
    int cnt = g_count[e];
    int m0 = blockIdx.x * 64;
    if (m0 >= cnt) return;
    int n0 = blockIdx.y * 64;
    const float* W = (e < NEXP) ? (wgu + (size_t)e * (2 * IDIM) * HID) : sgu;

    __shared__ float sX[16][64];
    __shared__ float sG[16][64];
    __shared__ float sU[16][64];

    int tid = threadIdx.x;
    int lr = tid >> 2, kq = tid & 3;       // loader: row 0..63, k-quad 0..3
    int mrow = m0 + lr;
    if (mrow > cnt - 1) mrow = cnt - 1;    // clamp padded rows to a valid token
    int tok = g_token[e * CAP + mrow];
    const float* xp = x + (size_t)tok * HID + kq * 4;
    const float* gp = W + (size_t)(n0 + lr) * HID + kq * 4;
    const float* up = W + (size_t)(IDIM + n0 + lr) * HID + kq * 4;

    int ty = tid >> 4, tx = tid & 15;
    float2 ag[4][2], au[4][2];
    #pragma unroll
    for (int i = 0; i < 4; i++)
        #pragma unroll
        for (int j = 0; j < 2; j++) {
            ag[i][j] = make_float2(0.f, 0.f);
            au[i][j] = make_float2(0.f, 0.f);
        }

    for (int k0 = 0; k0 < HID; k0 += 16) {
        float4 vx = *(const float4*)(xp + k0);
        float4 vg = *(const float4*)(gp + k0);
        float4 vu = *(const float4*)(up + k0);
        __syncthreads();
        sX[kq * 4 + 0][lr] = vx.x; sX[kq * 4 + 1][lr] = vx.y;
        sX[kq * 4 + 2][lr] = vx.z; sX[kq * 4 + 3][lr] = vx.w;
        sG[kq * 4 + 0][lr] = vg.x; sG[kq * 4 + 1][lr] = vg.y;
        sG[kq * 4 + 2][lr] = vg.z; sG[kq * 4 + 3][lr] = vg.w;
        sU[kq * 4 + 0][lr] = vu.x; sU[kq * 4 + 1][lr] = vu.y;
        sU[kq * 4 + 2][lr] = vu.z; sU[kq * 4 + 3][lr] = vu.w;
        __syncthreads();
        #pragma unroll
        for (int kk = 0; kk < 16; kk++) {
            float4 av = *(const float4*)&sX[kk][ty * 4];
            float4 gv = *(const float4*)&sG[kk][tx * 4];
            float4 uv = *(const float4*)&sU[kk][tx * 4];
            float a[4] = {av.x, av.y, av.z, av.w};
            float2 bg[2] = {make_float2(gv.x, gv.y), make_float2(gv.z, gv.w)};
            float2 bu[2] = {make_float2(uv.x, uv.y), make_float2(uv.z, uv.w)};
            #pragma unroll
            for (int i = 0; i < 4; i++) {
                float2 a2 = make_float2(a[i], a[i]);
                #pragma unroll
                for (int jp = 0; jp < 2; jp++) {
                    ag[i][jp] = ffma2(a2, bg[jp], ag[i][jp]);
                    au[i][jp] = ffma2(a2, bu[jp], au[i][jp]);
                }
            }
        }
    }
    #pragma unroll
    for (int i = 0; i < 4; i++) {
        int m = m0 + ty * 4 + i;
        if (m < cnt) {
            size_t r = (size_t)e * CAP + m;
            float gvals[4] = {ag[i][0].x, ag[i][0].y, ag[i][1].x, ag[i][1].y};
            float uvals[4] = {au[i][0].x, au[i][0].y, au[i][1].x, au[i][1].y};
            float4 o;
            o.x = silu_f(gvals[0]) * uvals[0];
            o.y = silu_f(gvals[1]) * uvals[1];
            o.z = silu_f(gvals[2]) * uvals[2];
            o.w = silu_f(gvals[3]) * uvals[3];
            *(float4*)(g_act + r * IDIM + n0 + tx * 4) = o;
        }
    }
}

// ---------------- 4) down GEMM, scaled by routing weight ----------------
__global__ void __launch_bounds__(256, 2)
down_kernel(const float* __restrict__ wdn,
            const float* __restrict__ sdn) {
    int e = blockIdx.z;
    int cnt = g_count[e];
    int m0 = blockIdx.x * 64;
    if (m0 >= cnt) return;
    int n0 = blockIdx.y * 64;   // output H columns
    const float* W = (e < NEXP) ? (wdn + (size_t)e * HID * IDIM) : sdn;

    __shared__ float sA[16][64];
    __shared__ float sB[16][64];

    int tid = threadIdx.x;
    int lr = tid >> 2, kq = tid & 3;
    int mrow = m0 + lr;
    if (mrow > cnt - 1) mrow = cnt - 1;
    const float* ap = g_act + ((size_t)e * CAP + mrow) * IDIM + kq * 4;
    const float* bp = W + (size_t)(n0 + lr) * IDIM + kq * 4;

    int ty = tid >> 4, tx = tid & 15;
    float2 acc[4][2];
    #pragma unroll
    for (int i = 0; i < 4; i++)
        #pragma unroll
        for (int j = 0; j < 2; j++) acc[i][j] = make_float2(0.f, 0.f);

    for (int k0 = 0; k0 < IDIM; k0 += 16) {
        float4 va = *(const float4*)(ap + k0);
        float4 vb = *(const float4*)(bp + k0);
        __syncthreads();
        sA[kq * 4 + 0][lr] = va.x; sA[kq * 4 + 1][lr] = va.y;
        sA[kq * 4 + 2][lr] = va.z; sA[kq * 4 + 3][lr] = va.w;
        sB[kq * 4 + 0][lr] = vb.x; sB[kq * 4 + 1][lr] = vb.y;
        sB[kq * 4 + 2][lr] = vb.z; sB[kq * 4 + 3][lr] = vb.w;
        __syncthreads();
        #pragma unroll
        for (int kk = 0; kk < 16; kk++) {
            float4 av = *(const float4*)&sA[kk][ty * 4];
            float4 bv = *(const float4*)&sB[kk][tx * 4];
            float a[4] = {av.x, av.y, av.z, av.w};
            float2 bb[2] = {make_float2(bv.x, bv.y), make_float2(bv.z, bv.w)};
            #pragma unroll
            for (int i = 0; i < 4; i++) {
                float2 a2 = make_float2(a[i], a[i]);
                #pragma unroll
                for (int jp = 0; jp < 2; jp++)
                    acc[i][jp] = ffma2(a2, bb[jp], acc[i][jp]);
            }
        }
    }
    #pragma unroll
    for (int i = 0; i < 4; i++) {
        int m = m0 + ty * 4 + i;
        if (m < cnt) {
            size_t r = (size_t)e * CAP + m;
            float w = g_wt[e * CAP + m];
            float4 o;
            o.x = acc[i][0].x * w; o.y = acc[i][0].y * w;
            o.z = acc[i][1].x * w; o.w = acc[i][1].y * w;
            *(float4*)(g_down + r * HID + n0 + tx * 4) = o;
        }
    }
}

// ---------------- 5) deterministic per-token combine ----------------
__global__ void combine_kernel(float* __restrict__ y) {
    int t = blockIdx.x;
    __shared__ int rows[NEXP];
    if (threadIdx.x < NEXP) rows[threadIdx.x] = g_rowid[threadIdx.x * T_TOK + t];
    __syncthreads();
    int h0 = threadIdx.x * 8;   // 256 threads * 8 = 2048 = H
    const float* sh = g_down + ((size_t)NEXP * CAP + t) * HID + h0;
    float4 s0 = *(const float4*)sh;
    float4 s1 = *(const float4*)(sh + 4);
    for (int e = 0; e < NEXP; e++) {
        int r = rows[e];
        if (r >= 0) {
            const float* p = g_down + (size_t)r * HID + h0;
            float4 a = *(const float4*)p;
            float4 b = *(const float4*)(p + 4);
            s0.x += a.x; s0.y += a.y; s0.z += a.z; s0.w += a.w;
            s1.x += b.x; s1.y += b.y; s1.z += b.z; s1.w += b.w;
        }
    }
    float* out = y + (size_t)t * HID + h0;
    *(float4*)out = s0;
    *(float4*)(out + 4) = s1;
}

// ---------------- launcher ----------------
extern "C" void kernel_launch(void* const* d_in, const int* in_sizes, int n_in,
                              void* d_out, int out_size) {
    const float* x    = (const float*)d_in[0];
    const float* gw   = (const float*)d_in[1];
    const float* bias = (const float*)d_in[2];
    const float* wgu  = (const float*)d_in[3];
    const float* wdn  = (const float*)d_in[4];
    const float* sgu  = (const float*)d_in[5];
    const float* sdn  = (const float*)d_in[6];
    float* y = (float*)d_out;

    router_kernel<<<T_TOK, 256>>>(x, gw, bias);
    build_lists_kernel<<<NE, T_TOK>>>();
    dim3 ga(CAP / 64, IDIM / 64, NE);
    gateup_kernel<<<ga, 256>>>(x, wgu, sgu);
    dim3 gd(CAP / 64, HID / 64, NE);
    down_kernel<<<gd, 256>>>(wdn, sdn);
    combine_kernel<<<T_TOK, 256>>>(y);
}

// round 6
// speedup vs baseline: 2.1099x; 2.1099x over previous
#include <cuda_runtime.h>
#include <cuda_bf16.h>
#include <cstdint>
#include <cstddef>

#define T_TOK 1024
#define HID   2048
#define IDIM  1024
#define NEXP  32
#define NGRP  8
#define EPG   4
#define TOPG  4
#define TOPK  8
#define NE    33      // 32 routed + 1 shared
#define CAP   1024
#define RSCALE 2.5f

// GEMM tiling
#define BK   32                 // fp32 k-chunk
#define STR  40                 // padded bf16 row stride (80B -> conflict-free ldmatrix)
#define ASZ  (128 * STR * 2)    // bytes per 128xBK bf16 tile = 10240
#define BUFB (4 * ASZ)          // Ahi,Alo,Bhi,Blo = 40960
#define SMEMB (2 * BUFB)        // double buffer = 81920

// ---------------- static scratch (no allocations allowed) ----------------
__device__ float g_combine[T_TOK * NEXP];
__device__ int   g_count[NE];
__device__ int   g_token[NE * CAP];
__device__ float g_wt[NE * CAP];
__device__ int   g_rowid[NEXP * T_TOK];                    // [e][t] -> row or -1
__device__ float g_act[(size_t)NE * CAP * IDIM];           // silu(g)*u rows
__device__ float g_down[(size_t)NE * CAP * HID];           // weighted down-proj rows

__device__ __forceinline__ float silu_f(float v) {
    return v / (1.0f + expf(-v));
}

__device__ __forceinline__ uint32_t smem_u32(const void* p) {
    uint32_t a;
    asm("{ .reg .u64 t; cvta.to.shared.u64 t, %1; cvt.u32.u64 %0, t; }"
        : "=r"(a) : "l"(p));
    return a;
}

__device__ __forceinline__ void ldm4(uint32_t* r, uint32_t addr) {
    asm volatile("ldmatrix.sync.aligned.m8n8.x4.shared.b16 {%0,%1,%2,%3}, [%4];"
        : "=r"(r[0]), "=r"(r[1]), "=r"(r[2]), "=r"(r[3]) : "r"(addr));
}
__device__ __forceinline__ void ldm2(uint32_t* r, uint32_t addr) {
    asm volatile("ldmatrix.sync.aligned.m8n8.x2.shared.b16 {%0,%1}, [%2];"
        : "=r"(r[0]), "=r"(r[1]) : "r"(addr));
}
__device__ __forceinline__ void mma16816(float* c, const uint32_t* a, const uint32_t* b) {
    asm volatile("mma.sync.aligned.m16n8k16.row.col.f32.bf16.bf16.f32 "
        "{%0,%1,%2,%3}, {%4,%5,%6,%7}, {%8,%9}, {%0,%1,%2,%3};"
        : "+f"(c[0]), "+f"(c[1]), "+f"(c[2]), "+f"(c[3])
        : "r"(a[0]), "r"(a[1]), "r"(a[2]), "r"(a[3]), "r"(b[0]), "r"(b[1]));
}

// split fp32x4 -> bf16 hi + bf16 lo, store 8B each
__device__ __forceinline__ void split_store(uint32_t ahi, uint32_t alo, float4 v) {
    __nv_bfloat16 h0 = __float2bfloat16(v.x), h1 = __float2bfloat16(v.y);
    __nv_bfloat16 h2 = __float2bfloat16(v.z), h3 = __float2bfloat16(v.w);
    __nv_bfloat16 l0 = __float2bfloat16(v.x - __bfloat162float(h0));
    __nv_bfloat16 l1 = __float2bfloat16(v.y - __bfloat162float(h1));
    __nv_bfloat16 l2 = __float2bfloat16(v.z - __bfloat162float(h2));
    __nv_bfloat16 l3 = __float2bfloat16(v.w - __bfloat162float(h3));
    unsigned long long H =
        (unsigned long long)__bfloat16_as_ushort(h0) |
        ((unsigned long long)__bfloat16_as_ushort(h1) << 16) |
        ((unsigned long long)__bfloat16_as_ushort(h2) << 32) |
        ((unsigned long long)__bfloat16_as_ushort(h3) << 48);
    unsigned long long L =
        (unsigned long long)__bfloat16_as_ushort(l0) |
        ((unsigned long long)__bfloat16_as_ushort(l1) << 16) |
        ((unsigned long long)__bfloat16_as_ushort(l2) << 32) |
        ((unsigned long long)__bfloat16_as_ushort(l3) << 48);
    asm volatile("st.shared.b64 [%0], %1;" :: "r"(ahi), "l"(H) : "memory");
    asm volatile("st.shared.b64 [%0], %1;" :: "r"(alo), "l"(L) : "memory");
}

// ---------------- 1) router ----------------
__global__ void router_kernel(const float* __restrict__ x,
                              const float* __restrict__ gw,
                              const float* __restrict__ bias) {
    __shared__ float sx[HID];
    __shared__ float slog[NEXP];
    int t = blockIdx.x;
    const float* xr = x + (size_t)t * HID;
    for (int k = threadIdx.x; k < HID; k += blockDim.x) sx[k] = xr[k];
    __syncthreads();
    int warp = threadIdx.x >> 5, lane = threadIdx.x & 31;
    for (int e = warp; e < NEXP; e += 8) {
        const float* w = gw + (size_t)e * HID;
        float acc = 0.f;
        for (int k = lane; k < HID; k += 32) acc = fmaf(sx[k], w[k], acc);
        #pragma unroll
        for (int o = 16; o; o >>= 1) acc += __shfl_down_sync(0xffffffffu, acc, o);
        if (lane == 0) slog[e] = acc;
    }
    __syncthreads();
    if (threadIdx.x == 0) {
        float s[NEXP], sr[NEXP];
        #pragma unroll
        for (int e = 0; e < NEXP; e++) {
            float sc = 1.f / (1.f + expf(-slog[e]));
            s[e] = sc;
            sr[e] = sc + bias[e];
        }
        float gs[NGRP];
        #pragma unroll
        for (int g = 0; g < NGRP; g++) {
            float m1 = -1e30f, m2 = -1e30f;
            #pragma unroll
            for (int j = 0; j < EPG; j++) {
                float v = sr[g * EPG + j];
                if (v > m1) { m2 = m1; m1 = v; }
                else if (v > m2) { m2 = v; }
            }
            gs[g] = m1 + m2;
        }
        bool gsel[NGRP];
        #pragma unroll
        for (int g = 0; g < NGRP; g++) gsel[g] = false;
        for (int it = 0; it < TOPG; it++) {
            float best = -1e30f; int bi = 0;
            for (int g = 0; g < NGRP; g++)
                if (!gsel[g] && gs[g] > best) { best = gs[g]; bi = g; }
            gsel[bi] = true;
        }
        bool taken[NEXP];
        #pragma unroll
        for (int e = 0; e < NEXP; e++) taken[e] = false;
        int ids[TOPK];
        for (int it = 0; it < TOPK; it++) {
            float best = -1e30f; int bi = 0;
            for (int e = 0; e < NEXP; e++)
                if (gsel[e >> 2] && !taken[e] && sr[e] > best) { best = sr[e]; bi = e; }
            taken[bi] = true;
            ids[it] = bi;
        }
        float sum = 0.f;
        for (int k = 0; k < TOPK; k++) sum += s[ids[k]];
        float inv = RSCALE / (sum + 1e-20f);
        float out[NEXP];
        #pragma unroll
        for (int e = 0; e < NEXP; e++) out[e] = 0.f;
        for (int k = 0; k < TOPK; k++) out[ids[k]] = s[ids[k]] * inv;
        #pragma unroll
        for (int e = 0; e < NEXP; e++) g_combine[t * NEXP + e] = out[e];
    }
}

// ---------------- 2) compact per-expert token lists ----------------
__global__ void build_lists_kernel() {
    int e = blockIdx.x;
    int t = threadIdx.x;
    __shared__ int sc[T_TOK];
    float w;
    int flag;
    if (e < NEXP) {
        w = g_combine[t * NEXP + e];
        flag = (w > 0.f) ? 1 : 0;
    } else {
        w = 1.0f;
        flag = 1;
    }
    sc[t] = flag;
    __syncthreads();
    for (int off = 1; off < T_TOK; off <<= 1) {
        int v = (t >= off) ? sc[t - off] : 0;
        __syncthreads();
        sc[t] += v;
        __syncthreads();
    }
    int pos = sc[t] - flag;
    if (flag) {
        g_token[e * CAP + pos] = t;
        g_wt[e * CAP + pos] = w;
    }
    if (e < NEXP) g_rowid[e * T_TOK + t] = flag ? (e * CAP + pos) : -1;
    if (t == T_TOK - 1) g_count[e] = sc[T_TOK - 1];
}

// ---------------- 3) gate_up GEMM via mma.sync (bf16 hi/lo 3-term split) ----
// CTA tile: M=128 rows, D = 128 cols interleaved (even=gate j, odd=up j).
__global__ void __launch_bounds__(256, 1)
gateup_mma(const float* __restrict__ x,
           const float* __restrict__ wgu,
           const float* __restrict__ sgu) {
    int e = blockIdx.z;
    int cnt = g_count[e];
    int m0 = blockIdx.x * 128;
    if (m0 >= cnt) return;
    int n0 = blockIdx.y * 64;
    const float* W = (e < NEXP) ? (wgu + (size_t)e * (2 * IDIM) * HID) : sgu;

    extern __shared__ char smem[];
    uint32_t sb = smem_u32(smem);
    int tid = threadIdx.x;
    int lane = tid & 31, wid = tid >> 5;

    // loader: thread -> (tile row, half of 32-float chunk)
    int lrow = tid >> 1, lhalf = tid & 1;
    int mrow = m0 + lrow; if (mrow > cnt - 1) mrow = cnt - 1;
    const float* aptr = x + (size_t)g_token[e * CAP + mrow] * HID + lhalf * 16;
    int jcol = lrow >> 1;
    int wrow = (lrow & 1) ? (IDIM + n0 + jcol) : (n0 + jcol);
    const float* bptr = W + (size_t)wrow * HID + lhalf * 16;
    uint32_t soff = (uint32_t)(lrow * STR + lhalf * 16) * 2;

    int wm0 = (wid >> 2) * 64, wn0 = (wid & 3) * 32;
    uint32_t a_r = (uint32_t)(wm0 + (lane & 15));
    uint32_t a_c8 = (uint32_t)((lane >> 4) * 8);
    uint32_t b_r = (uint32_t)(wn0 + (lane & 7));
    uint32_t b_c8 = (uint32_t)(((lane >> 3) & 1) * 8);

    float acc[4][4][4];
    #pragma unroll
    for (int mi = 0; mi < 4; mi++)
        #pragma unroll
        for (int ni = 0; ni < 4; ni++)
            #pragma unroll
            for (int q = 0; q < 4; q++) acc[mi][ni][q] = 0.f;

    float4 ra[4], rb[4];
    // prologue: chunk 0
    #pragma unroll
    for (int q = 0; q < 4; q++) {
        ra[q] = *(const float4*)(aptr + q * 4);
        rb[q] = *(const float4*)(bptr + q * 4);
    }
    #pragma unroll
    for (int q = 0; q < 4; q++) {
        uint32_t o = soff + q * 8;
        split_store(sb + o, sb + ASZ + o, ra[q]);
        split_store(sb + 2 * ASZ + o, sb + 3 * ASZ + o, rb[q]);
    }
    __syncthreads();

    const int NC = HID / BK;  // 64
    for (int c = 0; c < NC; c++) {
        if (c + 1 < NC) {
            const float* ap = aptr + (c + 1) * BK;
            const float* bp = bptr + (c + 1) * BK;
            #pragma unroll
            for (int q = 0; q < 4; q++) {
                ra[q] = *(const float4*)(ap + q * 4);
                rb[q] = *(const float4*)(bp + q * 4);
            }
        }
        uint32_t cur = sb + (uint32_t)(c & 1) * BUFB;
        #pragma unroll
        for (int kh = 0; kh < 2; kh++) {
            uint32_t ah[4][4], al[4][4], bh[4][2], bl[4][2];
            #pragma unroll
            for (int mi = 0; mi < 4; mi++) {
                uint32_t ad = cur + ((a_r + mi * 16) * STR + kh * 16 + a_c8) * 2;
                ldm4(ah[mi], ad);
                ldm4(al[mi], ad + ASZ);
            }
            #pragma unroll
            for (int ni = 0; ni < 4; ni++) {
                uint32_t bd = cur + 2 * ASZ + ((b_r + ni * 8) * STR + kh * 16 + b_c8) * 2;
                ldm2(bh[ni], bd);
                ldm2(bl[ni], bd + ASZ);
            }
            #pragma unroll
            for (int mi = 0; mi < 4; mi++)
                #pragma unroll
                for (int ni = 0; ni < 4; ni++) {
                    mma16816(acc[mi][ni], ah[mi], bh[ni]);
                    mma16816(acc[mi][ni], ah[mi], bl[ni]);
                    mma16816(acc[mi][ni], al[mi], bh[ni]);
                }
        }
        if (c + 1 < NC) {
            uint32_t nb = sb + (uint32_t)((c + 1) & 1) * BUFB;
            #pragma unroll
            for (int q = 0; q < 4; q++) {
                uint32_t o = soff + q * 8;
                split_store(nb + o, nb + ASZ + o, ra[q]);
                split_store(nb + 2 * ASZ + o, nb + 3 * ASZ + o, rb[q]);
            }
        }
        __syncthreads();
    }

    // epilogue: c0=gate, c1=up for col j; rows g and g+8
    int g = lane >> 2, tc = (lane & 3) * 2;
    #pragma unroll
    for (int mi = 0; mi < 4; mi++) {
        int r0 = m0 + wm0 + mi * 16 + g;
        int r1 = r0 + 8;
        #pragma unroll
        for (int ni = 0; ni < 4; ni++) {
            int col = n0 + ((wn0 + ni * 8 + tc) >> 1);
            if (r0 < cnt)
                g_act[((size_t)e * CAP + r0) * IDIM + col] =
                    silu_f(acc[mi][ni][0]) * acc[mi][ni][1];
            if (r1 < cnt)
                g_act[((size_t)e * CAP + r1) * IDIM + col] =
                    silu_f(acc[mi][ni][2]) * acc[mi][ni][3];
        }
    }
}

// ---------------- 4) down GEMM via mma.sync, scaled by routing weight -------
__global__ void __launch_bounds__(256, 1)
down_mma(const float* __restrict__ wdn,
         const float* __restrict__ sdn) {
    int e = blockIdx.z;
    int cnt = g_count[e];
    int m0 = blockIdx.x * 128;
    if (m0 >= cnt) return;
    int n0 = blockIdx.y * 128;
    const float* W = (e < NEXP) ? (wdn + (size_t)e * HID * IDIM) : sdn;

    extern __shared__ char smem[];
    uint32_t sb = smem_u32(smem);
    int tid = threadIdx.x;
    int lane = tid & 31, wid = tid >> 5;

    int lrow = tid >> 1, lhalf = tid & 1;
    int mrow = m0 + lrow; if (mrow > cnt - 1) mrow = cnt - 1;
    const float* aptr = g_act + ((size_t)e * CAP + mrow) * IDIM + lhalf * 16;
    const float* bptr = W + (size_t)(n0 + lrow) * IDIM + lhalf * 16;
    uint32_t soff = (uint32_t)(lrow * STR + lhalf * 16) * 2;

    int wm0 = (wid >> 2) * 64, wn0 = (wid & 3) * 32;
    uint32_t a_r = (uint32_t)(wm0 + (lane & 15));
    uint32_t a_c8 = (uint32_t)((lane >> 4) * 8);
    uint32_t b_r = (uint32_t)(wn0 + (lane & 7));
    uint32_t b_c8 = (uint32_t)(((lane >> 3) & 1) * 8);

    float acc[4][4][4];
    #pragma unroll
    for (int mi = 0; mi < 4; mi++)
        #pragma unroll
        for (int ni = 0; ni < 4; ni++)
            #pragma unroll
            for (int q = 0; q < 4; q++) acc[mi][ni][q] = 0.f;

    float4 ra[4], rb[4];
    #pragma unroll
    for (int q = 0; q < 4; q++) {
        ra[q] = *(const float4*)(aptr + q * 4);
        rb[q] = *(const float4*)(bptr + q * 4);
    }
    #pragma unroll
    for (int q = 0; q < 4; q++) {
        uint32_t o = soff + q * 8;
        split_store(sb + o, sb + ASZ + o, ra[q]);
        split_store(sb + 2 * ASZ + o, sb + 3 * ASZ + o, rb[q]);
    }
    __syncthreads();

    const int NC = IDIM / BK;  // 32
    for (int c = 0; c < NC; c++) {
        if (c + 1 < NC) {
            const float* ap = aptr + (c + 1) * BK;
            const float* bp = bptr + (c + 1) * BK;
            #pragma unroll
            for (int q = 0; q < 4; q++) {
                ra[q] = *(const float4*)(ap + q * 4);
                rb[q] = *(const float4*)(bp + q * 4);
            }
        }
        uint32_t cur = sb + (uint32_t)(c & 1) * BUFB;
        #pragma unroll
        for (int kh = 0; kh < 2; kh++) {
            uint32_t ah[4][4], al[4][4], bh[4][2], bl[4][2];
            #pragma unroll
            for (int mi = 0; mi < 4; mi++) {
                uint32_t ad = cur + ((a_r + mi * 16) * STR + kh * 16 + a_c8) * 2;
                ldm4(ah[mi], ad);
                ldm4(al[mi], ad + ASZ);
            }
            #pragma unroll
            for (int ni = 0; ni < 4; ni++) {
                uint32_t bd = cur + 2 * ASZ + ((b_r + ni * 8) * STR + kh * 16 + b_c8) * 2;
                ldm2(bh[ni], bd);
                ldm2(bl[ni], bd + ASZ);
            }
            #pragma unroll
            for (int mi = 0; mi < 4; mi++)
                #pragma unroll
                for (int ni = 0; ni < 4; ni++) {
                    mma16816(acc[mi][ni], ah[mi], bh[ni]);
                    mma16816(acc[mi][ni], ah[mi], bl[ni]);
                    mma16816(acc[mi][ni], al[mi], bh[ni]);
                }
        }
        if (c + 1 < NC) {
            uint32_t nb = sb + (uint32_t)((c + 1) & 1) * BUFB;
            #pragma unroll
            for (int q = 0; q < 4; q++) {
                uint32_t o = soff + q * 8;
                split_store(nb + o, nb + ASZ + o, ra[q]);
                split_store(nb + 2 * ASZ + o, nb + 3 * ASZ + o, rb[q]);
            }
        }
        __syncthreads();
    }

    int g = lane >> 2, tc = (lane & 3) * 2;
    #pragma unroll
    for (int mi = 0; mi < 4; mi++) {
        int r0 = m0 + wm0 + mi * 16 + g;
        int r1 = r0 + 8;
        float w0 = (r0 < cnt) ? g_wt[e * CAP + r0] : 0.f;
        float w1 = (r1 < cnt) ? g_wt[e * CAP + r1] : 0.f;
        #pragma unroll
        for (int ni = 0; ni < 4; ni++) {
            int col = n0 + wn0 + ni * 8 + tc;
            if (r0 < cnt) {
                float2 v = make_float2(acc[mi][ni][0] * w0, acc[mi][ni][1] * w0);
                *(float2*)(g_down + ((size_t)e * CAP + r0) * HID + col) = v;
            }
            if (r1 < cnt) {
                float2 v = make_float2(acc[mi][ni][2] * w1, acc[mi][ni][3] * w1);
                *(float2*)(g_down + ((size_t)e * CAP + r1) * HID + col) = v;
            }
        }
    }
}

// ---------------- 5) deterministic per-token combine ----------------
__global__ void combine_kernel(float* __restrict__ y) {
    int t = blockIdx.x;
    __shared__ int rows[NEXP];
    if (threadIdx.x < NEXP) rows[threadIdx.x] = g_rowid[threadIdx.x * T_TOK + t];
    __syncthreads();
    int h0 = threadIdx.x * 8;
    const float* sh = g_down + ((size_t)NEXP * CAP + t) * HID + h0;
    float4 s0 = *(const float4*)sh;
    float4 s1 = *(const float4*)(sh + 4);
    for (int e = 0; e < NEXP; e++) {
        int r = rows[e];
        if (r >= 0) {
            const float* p = g_down + (size_t)r * HID + h0;
            float4 a = *(const float4*)p;
            float4 b = *(const float4*)(p + 4);
            s0.x += a.x; s0.y += a.y; s0.z += a.z; s0.w += a.w;
            s1.x += b.x; s1.y += b.y; s1.z += b.z; s1.w += b.w;
        }
    }
    float* out = y + (size_t)t * HID + h0;
    *(float4*)out = s0;
    *(float4*)(out + 4) = s1;
}

// ---------------- launcher ----------------
extern "C" void kernel_launch(void* const* d_in, const int* in_sizes, int n_in,
                              void* d_out, int out_size) {
    const float* x    = (const float*)d_in[0];
    const float* gw   = (const float*)d_in[1];
    const float* bias = (const float*)d_in[2];
    const float* wgu  = (const float*)d_in[3];
    const float* wdn  = (const float*)d_in[4];
    const float* sgu  = (const float*)d_in[5];
    const float* sdn  = (const float*)d_in[6];
    float* y = (float*)d_out;

    cudaFuncSetAttribute(gateup_mma, cudaFuncAttributeMaxDynamicSharedMemorySize, SMEMB);
    cudaFuncSetAttribute(down_mma, cudaFuncAttributeMaxDynamicSharedMemorySize, SMEMB);

    router_kernel<<<T_TOK, 256>>>(x, gw, bias);
    build_lists_kernel<<<NE, T_TOK>>>();
    dim3 ga(CAP / 128, IDIM / 64, NE);
    gateup_mma<<<ga, 256, SMEMB>>>(x, wgu, sgu);
    dim3 gd(CAP / 128, HID / 128, NE);
    down_mma<<<gd, 256, SMEMB>>>(wdn, sdn);
    combine_kernel<<<T_TOK, 256>>>(y);
}

// round 9
// speedup vs baseline: 2.1401x; 1.0143x over previous
#include <cuda_runtime.h>
#include <cuda_bf16.h>
#include <cstdint>
#include <cstddef>

#define T_TOK 1024
#define HID   2048
#define IDIM  1024
#define NEXP  32
#define NGRP  8
#define EPG   4
#define TOPG  4
#define TOPK  8
#define NE    33      // 32 routed + 1 shared
#define CAP   1024
#define RSCALE 2.5f

// GEMM tiling
#define BK   32                 // fp32 k-chunk
#define STR  40                 // padded bf16 row stride (80B -> conflict-free ldmatrix)
#define ASZ  (128 * STR * 2)    // bytes per 128xBK bf16 tile = 10240
#define BUFB (4 * ASZ)          // Ahi,Alo,Bhi,Blo = 40960
#define SMEMB (2 * BUFB)        // double buffer = 81920

// ---------------- static scratch (no allocations allowed) ----------------
__device__ float g_combine[T_TOK * NEXP];
__device__ int   g_count[NE];
__device__ int   g_token[NE * CAP];
__device__ float g_wt[NE * CAP];
__device__ int   g_rowid[NEXP * T_TOK];                    // [e][t] -> row or -1
__device__ float g_act[(size_t)NE * CAP * IDIM];           // silu(g)*u rows
__device__ float g_down[(size_t)NE * CAP * HID];           // weighted down-proj rows

__device__ __forceinline__ float silu_f(float v) {
    return v / (1.0f + expf(-v));
}

__device__ __forceinline__ uint32_t smem_u32(const void* p) {
    uint32_t a;
    asm("{ .reg .u64 t; cvta.to.shared.u64 t, %1; cvt.u32.u64 %0, t; }"
        : "=r"(a) : "l"(p));
    return a;
}

__device__ __forceinline__ void ldm4(uint32_t* r, uint32_t addr) {
    asm volatile("ldmatrix.sync.aligned.m8n8.x4.shared.b16 {%0,%1,%2,%3}, [%4];"
        : "=r"(r[0]), "=r"(r[1]), "=r"(r[2]), "=r"(r[3]) : "r"(addr));
}
__device__ __forceinline__ void mma16816(float* c, const uint32_t* a, const uint32_t* b) {
    asm volatile("mma.sync.aligned.m16n8k16.row.col.f32.bf16.bf16.f32 "
        "{%0,%1,%2,%3}, {%4,%5,%6,%7}, {%8,%9}, {%0,%1,%2,%3};"
        : "+f"(c[0]), "+f"(c[1]), "+f"(c[2]), "+f"(c[3])
        : "r"(a[0]), "r"(a[1]), "r"(a[2]), "r"(a[3]), "r"(b[0]), "r"(b[1]));
}

// split fp32x4 -> bf16 hi + bf16 lo, store 8B each
__device__ __forceinline__ void split_store(uint32_t ahi, uint32_t alo, float4 v) {
    __nv_bfloat16 h0 = __float2bfloat16(v.x), h1 = __float2bfloat16(v.y);
    __nv_bfloat16 h2 = __float2bfloat16(v.z), h3 = __float2bfloat16(v.w);
    __nv_bfloat16 l0 = __float2bfloat16(v.x - __bfloat162float(h0));
    __nv_bfloat16 l1 = __float2bfloat16(v.y - __bfloat162float(h1));
    __nv_bfloat16 l2 = __float2bfloat16(v.z - __bfloat162float(h2));
    __nv_bfloat16 l3 = __float2bfloat16(v.w - __bfloat162float(h3));
    unsigned long long H =
        (unsigned long long)__bfloat16_as_ushort(h0) |
        ((unsigned long long)__bfloat16_as_ushort(h1) << 16) |
        ((unsigned long long)__bfloat16_as_ushort(h2) << 32) |
        ((unsigned long long)__bfloat16_as_ushort(h3) << 48);
    unsigned long long L =
        (unsigned long long)__bfloat16_as_ushort(l0) |
        ((unsigned long long)__bfloat16_as_ushort(l1) << 16) |
        ((unsigned long long)__bfloat16_as_ushort(l2) << 32) |
        ((unsigned long long)__bfloat16_as_ushort(l3) << 48);
    asm volatile("st.shared.b64 [%0], %1;" :: "r"(ahi), "l"(H) : "memory");
    asm volatile("st.shared.b64 [%0], %1;" :: "r"(alo), "l"(L) : "memory");
}

// ---------------- 1) router ----------------
__global__ void router_kernel(const float* __restrict__ x,
                              const float* __restrict__ gw,
                              const float* __restrict__ bias) {
    __shared__ float sx[HID];
    __shared__ float slog[NEXP];
    int t = blockIdx.x;
    const float* xr = x + (size_t)t * HID;
    for (int k = threadIdx.x; k < HID; k += blockDim.x) sx[k] = xr[k];
    __syncthreads();
    int warp = threadIdx.x >> 5, lane = threadIdx.x & 31;
    for (int e = warp; e < NEXP; e += 8) {
        const float* w = gw + (size_t)e * HID;
        float acc = 0.f;
        for (int k = lane; k < HID; k += 32) acc = fmaf(sx[k], w[k], acc);
        #pragma unroll
        for (int o = 16; o; o >>= 1) acc += __shfl_down_sync(0xffffffffu, acc, o);
        if (lane == 0) slog[e] = acc;
    }
    __syncthreads();
    if (threadIdx.x == 0) {
        float s[NEXP], sr[NEXP];
        #pragma unroll
        for (int e = 0; e < NEXP; e++) {
            float sc = 1.f / (1.f + expf(-slog[e]));
            s[e] = sc;
            sr[e] = sc + bias[e];
        }
        float gs[NGRP];
        #pragma unroll
        for (int g = 0; g < NGRP; g++) {
            float m1 = -1e30f, m2 = -1e30f;
            #pragma unroll
            for (int j = 0; j < EPG; j++) {
                float v = sr[g * EPG + j];
                if (v > m1) { m2 = m1; m1 = v; }
                else if (v > m2) { m2 = v; }
            }
            gs[g] = m1 + m2;
        }
        bool gsel[NGRP];
        #pragma unroll
        for (int g = 0; g < NGRP; g++) gsel[g] = false;
        for (int it = 0; it < TOPG; it++) {
            float best = -1e30f; int bi = 0;
            for (int g = 0; g < NGRP; g++)
                if (!gsel[g] && gs[g] > best) { best = gs[g]; bi = g; }
            gsel[bi] = true;
        }
        bool taken[NEXP];
        #pragma unroll
        for (int e = 0; e < NEXP; e++) taken[e] = false;
        int ids[TOPK];
        for (int it = 0; it < TOPK; it++) {
            float best = -1e30f; int bi = 0;
            for (int e = 0; e < NEXP; e++)
                if (gsel[e >> 2] && !taken[e] && sr[e] > best) { best = sr[e]; bi = e; }
            taken[bi] = true;
            ids[it] = bi;
        }
        float sum = 0.f;
        for (int k = 0; k < TOPK; k++) sum += s[ids[k]];
        float inv = RSCALE / (sum + 1e-20f);
        float out[NEXP];
        #pragma unroll
        for (int e = 0; e < NEXP; e++) out[e] = 0.f;
        for (int k = 0; k < TOPK; k++) out[ids[k]] = s[ids[k]] * inv;
        #pragma unroll
        for (int e = 0; e < NEXP; e++) g_combine[t * NEXP + e] = out[e];
    }
}

// ---------------- 2) compact per-expert token lists ----------------
__global__ void build_lists_kernel() {
    int e = blockIdx.x;
    int t = threadIdx.x;
    __shared__ int sc[T_TOK];
    float w;
    int flag;
    if (e < NEXP) {
        w = g_combine[t * NEXP + e];
        flag = (w > 0.f) ? 1 : 0;
    } else {
        w = 1.0f;
        flag = 1;
    }
    sc[t] = flag;
    __syncthreads();
    for (int off = 1; off < T_TOK; off <<= 1) {
        int v = (t >= off) ? sc[t - off] : 0;
        __syncthreads();
        sc[t] += v;
        __syncthreads();
    }
    int pos = sc[t] - flag;
    if (flag) {
        g_token[e * CAP + pos] = t;
        g_wt[e * CAP + pos] = w;
    }
    if (e < NEXP) g_rowid[e * T_TOK + t] = flag ? (e * CAP + pos) : -1;
    if (t == T_TOK - 1) g_count[e] = sc[T_TOK - 1];
}

// ---------------- 3) gate_up GEMM via mma.sync (bf16 hi/lo 3-term split) ----
// CTA tile: M=128 rows, D = 128 cols interleaved (even=gate j, odd=up j).
// 512 threads = 16 warps, each computing a 32x32 sub-tile.
__global__ void __launch_bounds__(512, 1)
gateup_mma(const float* __restrict__ x,
           const float* __restrict__ wgu,
           const float* __restrict__ sgu) {
    int e = blockIdx.z;
    int cnt = g_count[e];
    int m0 = blockIdx.x * 128;
    if (m0 >= cnt) return;
    int n0 = blockIdx.y * 64;
    const float* W = (e < NEXP) ? (wgu + (size_t)e * (2 * IDIM) * HID) : sgu;

    extern __shared__ char smem[];
    uint32_t sb = smem_u32(smem);
    int tid = threadIdx.x;
    int lane = tid & 31, wid = tid >> 5;

    // loader: 4 threads per tile row, each covers 8 floats of the 32-float chunk
    int lrow = tid >> 2, lquad = tid & 3;
    int mrow = m0 + lrow; if (mrow > cnt - 1) mrow = cnt - 1;
    const float* aptr = x + (size_t)g_token[e * CAP + mrow] * HID + lquad * 8;
    int jcol = lrow >> 1;
    int wrow = (lrow & 1) ? (IDIM + n0 + jcol) : (n0 + jcol);
    const float* bptr = W + (size_t)wrow * HID + lquad * 8;
    uint32_t soff = (uint32_t)(lrow * STR + lquad * 8) * 2;

    // warp grid 4x4: each warp 32 rows x 32 cols
    int wm0 = (wid >> 2) * 32, wn0 = (wid & 3) * 32;
    uint32_t a_r = (uint32_t)(wm0 + (lane & 15));
    uint32_t a_c8 = (uint32_t)((lane >> 4) * 8);
    // B ldm4: two n8 tiles per load (16 cols x 16 k)
    uint32_t b_row = (uint32_t)((lane & 7) + ((lane >> 4) << 3));
    uint32_t b_k8 = (uint32_t)(((lane >> 3) & 1) * 8);

    float acc[2][4][4];
    #pragma unroll
    for (int mi = 0; mi < 2; mi++)
        #pragma unroll
        for (int ni = 0; ni < 4; ni++)
            #pragma unroll
            for (int q = 0; q < 4; q++) acc[mi][ni][q] = 0.f;

    float4 ra[2], rb[2];
    #pragma unroll
    for (int q = 0; q < 2; q++) {
        ra[q] = *(const float4*)(aptr + q * 4);
        rb[q] = *(const float4*)(bptr + q * 4);
    }
    #pragma unroll
    for (int q = 0; q < 2; q++) {
        uint32_t o = soff + q * 8;
        split_store(sb + o, sb + ASZ + o, ra[q]);
        split_store(sb + 2 * ASZ + o, sb + 3 * ASZ + o, rb[q]);
    }
    __syncthreads();

    const int NC = HID / BK;  // 64
    for (int c = 0; c < NC; c++) {
        if (c + 1 < NC) {
            const float* ap = aptr + (c + 1) * BK;
            const float* bp = bptr + (c + 1) * BK;
            #pragma unroll
            for (int q = 0; q < 2; q++) {
                ra[q] = *(const float4*)(ap + q * 4);
                rb[q] = *(const float4*)(bp + q * 4);
            }
        }
        uint32_t cur = sb + (uint32_t)(c & 1) * BUFB;
        #pragma unroll
        for (int kh = 0; kh < 2; kh++) {
            uint32_t ah[2][4], al[2][4], bh[2][4], bl[2][4];
            #pragma unroll
            for (int mi = 0; mi < 2; mi++) {
                uint32_t ad = cur + ((a_r + mi * 16) * STR + kh * 16 + a_c8) * 2;
                ldm4(ah[mi], ad);
                ldm4(al[mi], ad + ASZ);
            }
            #pragma unroll
            for (int nj = 0; nj < 2; nj++) {
                uint32_t bd = cur + 2 * ASZ +
                    ((wn0 + nj * 16 + b_row) * STR + kh * 16 + b_k8) * 2;
                ldm4(bh[nj], bd);
                ldm4(bl[nj], bd + ASZ);
            }
            #pragma unroll
            for (int mi = 0; mi < 2; mi++)
                #pragma unroll
                for (int ni = 0; ni < 4; ni++) {
                    const uint32_t* bhp = &bh[ni >> 1][(ni & 1) * 2];
                    const uint32_t* blp = &bl[ni >> 1][(ni & 1) * 2];
                    mma16816(acc[mi][ni], ah[mi], bhp);
                    mma16816(acc[mi][ni], ah[mi], blp);
                    mma16816(acc[mi][ni], al[mi], bhp);
                }
        }
        if (c + 1 < NC) {
            uint32_t nb = sb + (uint32_t)((c + 1) & 1) * BUFB;
            #pragma unroll
            for (int q = 0; q < 2; q++) {
                uint32_t o = soff + q * 8;
                split_store(nb + o, nb + ASZ + o, ra[q]);
                split_store(nb + 2 * ASZ + o, nb + 3 * ASZ + o, rb[q]);
            }
        }
        __syncthreads();
    }

    // epilogue: c0=gate, c1=up for col j; rows g and g+8
    int g = lane >> 2, tc = (lane & 3) * 2;
    #pragma unroll
    for (int mi = 0; mi < 2; mi++) {
        int r0 = m0 + wm0 + mi * 16 + g;
        int r1 = r0 + 8;
        #pragma unroll
        for (int ni = 0; ni < 4; ni++) {
            int col = n0 + ((wn0 + ni * 8 + tc) >> 1);
            if (r0 < cnt)
                g_act[((size_t)e * CAP + r0) * IDIM + col] =
                    silu_f(acc[mi][ni][0]) * acc[mi][ni][1];
            if (r1 < cnt)
                g_act[((size_t)e * CAP + r1) * IDIM + col] =
                    silu_f(acc[mi][ni][2]) * acc[mi][ni][3];
        }
    }
}

// ---------------- 4) down GEMM via mma.sync, scaled by routing weight -------
__global__ void __launch_bounds__(512, 1)
down_mma(const float* __restrict__ wdn,
         const float* __restrict__ sdn) {
    int e = blockIdx.z;
    int cnt = g_count[e];
    int m0 = blockIdx.x * 128;
    if (m0 >= cnt) return;
    int n0 = blockIdx.y * 128;
    const float* W = (e < NEXP) ? (wdn + (size_t)e * HID * IDIM) : sdn;

    extern __shared__ char smem[];
    uint32_t sb = smem_u32(smem);
    int tid = threadIdx.x;
    int lane = tid & 31, wid = tid >> 5;

    int lrow = tid >> 2, lquad = tid & 3;
    int mrow = m0 + lrow; if (mrow > cnt - 1) mrow = cnt - 1;
    const float* aptr = g_act + ((size_t)e * CAP + mrow) * IDIM + lquad * 8;
    const float* bptr = W + (size_t)(n0 + lrow) * IDIM + lquad * 8;
    uint32_t soff = (uint32_t)(lrow * STR + lquad * 8) * 2;

    int wm0 = (wid >> 2) * 32, wn0 = (wid & 3) * 32;
    uint32_t a_r = (uint32_t)(wm0 + (lane & 15));
    uint32_t a_c8 = (uint32_t)((lane >> 4) * 8);
    uint32_t b_row = (uint32_t)((lane & 7) + ((lane >> 4) << 3));
    uint32_t b_k8 = (uint32_t)(((lane >> 3) & 1) * 8);

    float acc[2][4][4];
    #pragma unroll
    for (int mi = 0; mi < 2; mi++)
        #pragma unroll
        for (int ni = 0; ni < 4; ni++)
            #pragma unroll
            for (int q = 0; q < 4; q++) acc[mi][ni][q] = 0.f;

    float4 ra[2], rb[2];
    #pragma unroll
    for (int q = 0; q < 2; q++) {
        ra[q] = *(const float4*)(aptr + q * 4);
        rb[q] = *(const float4*)(bptr + q * 4);
    }
    #pragma unroll
    for (int q = 0; q < 2; q++) {
        uint32_t o = soff + q * 8;
        split_store(sb + o, sb + ASZ + o, ra[q]);
        split_store(sb + 2 * ASZ + o, sb + 3 * ASZ + o, rb[q]);
    }
    __syncthreads();

    const int NC = IDIM / BK;  // 32
    for (int c = 0; c < NC; c++) {
        if (c + 1 < NC) {
            const float* ap = aptr + (c + 1) * BK;
            const float* bp = bptr + (c + 1) * BK;
            #pragma unroll
            for (int q = 0; q < 2; q++) {
                ra[q] = *(const float4*)(ap + q * 4);
                rb[q] = *(const float4*)(bp + q * 4);
            }
        }
        uint32_t cur = sb + (uint32_t)(c & 1) * BUFB;
        #pragma unroll
        for (int kh = 0; kh < 2; kh++) {
            uint32_t ah[2][4], al[2][4], bh[2][4], bl[2][4];
            #pragma unroll
            for (int mi = 0; mi < 2; mi++) {
                uint32_t ad = cur + ((a_r + mi * 16) * STR + kh * 16 + a_c8) * 2;
                ldm4(ah[mi], ad);
                ldm4(al[mi], ad + ASZ);
            }
            #pragma unroll
            for (int nj = 0; nj < 2; nj++) {
                uint32_t bd = cur + 2 * ASZ +
                    ((wn0 + nj * 16 + b_row) * STR + kh * 16 + b_k8) * 2;
                ldm4(bh[nj], bd);
                ldm4(bl[nj], bd + ASZ);
            }
            #pragma unroll
            for (int mi = 0; mi < 2; mi++)
                #pragma unroll
                for (int ni = 0; ni < 4; ni++) {
                    const uint32_t* bhp = &bh[ni >> 1][(ni & 1) * 2];
                    const uint32_t* blp = &bl[ni >> 1][(ni & 1) * 2];
                    mma16816(acc[mi][ni], ah[mi], bhp);
                    mma16816(acc[mi][ni], ah[mi], blp);
                    mma16816(acc[mi][ni], al[mi], bhp);
                }
        }
        if (c + 1 < NC) {
            uint32_t nb = sb + (uint32_t)((c + 1) & 1) * BUFB;
            #pragma unroll
            for (int q = 0; q < 2; q++) {
                uint32_t o = soff + q * 8;
                split_store(nb + o, nb + ASZ + o, ra[q]);
                split_store(nb + 2 * ASZ + o, nb + 3 * ASZ + o, rb[q]);
            }
        }
        __syncthreads();
    }

    int g = lane >> 2, tc = (lane & 3) * 2;
    #pragma unroll
    for (int mi = 0; mi < 2; mi++) {
        int r0 = m0 + wm0 + mi * 16 + g;
        int r1 = r0 + 8;
        float w0 = (r0 < cnt) ? g_wt[e * CAP + r0] : 0.f;
        float w1 = (r1 < cnt) ? g_wt[e * CAP + r1] : 0.f;
        #pragma unroll
        for (int ni = 0; ni < 4; ni++) {
            int col = n0 + wn0 + ni * 8 + tc;
            if (r0 < cnt) {
                float2 v = make_float2(acc[mi][ni][0] * w0, acc[mi][ni][1] * w0);
                *(float2*)(g_down + ((size_t)e * CAP + r0) * HID + col) = v;
            }
            if (r1 < cnt) {
                float2 v = make_float2(acc[mi][ni][2] * w1, acc[mi][ni][3] * w1);
                *(float2*)(g_down + ((size_t)e * CAP + r1) * HID + col) = v;
            }
        }
    }
}

// ---------------- 5) deterministic per-token combine ----------------
__global__ void combine_kernel(float* __restrict__ y) {
    int t = blockIdx.x;
    __shared__ int rows[NEXP];
    if (threadIdx.x < NEXP) rows[threadIdx.x] = g_rowid[threadIdx.x * T_TOK + t];
    __syncthreads();
    int h0 = threadIdx.x * 8;
    const float* sh = g_down + ((size_t)NEXP * CAP + t) * HID + h0;
    float4 s0 = *(const float4*)sh;
    float4 s1 = *(const float4*)(sh + 4);
    for (int e = 0; e < NEXP; e++) {
        int r = rows[e];
        if (r >= 0) {
            const float* p = g_down + (size_t)r * HID + h0;
            float4 a = *(const float4*)p;
            float4 b = *(const float4*)(p + 4);
            s0.x += a.x; s0.y += a.y; s0.z += a.z; s0.w += a.w;
            s1.x += b.x; s1.y += b.y; s1.z += b.z; s1.w += b.w;
        }
    }
    float* out = y + (size_t)t * HID + h0;
    *(float4*)out = s0;
    *(float4*)(out + 4) = s1;
}

// ---------------- launcher ----------------
extern "C" void kernel_launch(void* const* d_in, const int* in_sizes, int n_in,
                              void* d_out, int out_size) {
    const float* x    = (const float*)d_in[0];
    const float* gw   = (const float*)d_in[1];
    const float* bias = (const float*)d_in[2];
    const float* wgu  = (const float*)d_in[3];
    const float* wdn  = (const float*)d_in[4];
    const float* sgu  = (const float*)d_in[5];
    const float* sdn  = (const float*)d_in[6];
    float* y = (float*)d_out;

    cudaFuncSetAttribute(gateup_mma, cudaFuncAttributeMaxDynamicSharedMemorySize, SMEMB);
    cudaFuncSetAttribute(down_mma, cudaFuncAttributeMaxDynamicSharedMemorySize, SMEMB);

    router_kernel<<<T_TOK, 256>>>(x, gw, bias);
    build_lists_kernel<<<NE, T_TOK>>>();
    dim3 ga(CAP / 128, IDIM / 64, NE);
    gateup_mma<<<ga, 512, SMEMB>>>(x, wgu, sgu);
    dim3 gd(CAP / 128, HID / 128, NE);
    down_mma<<<gd, 512, SMEMB>>>(wdn, sdn);
    combine_kernel<<<T_TOK, 256>>>(y);
}

// round 10
// speedup vs baseline: 2.4901x; 1.1635x over previous
#include <cuda_runtime.h>
#include <cuda_fp16.h>
#include <cstdint>
#include <cstddef>

#define T_TOK 1024
#define HID   2048
#define IDIM  1024
#define NEXP  32
#define NGRP  8
#define EPG   4
#define TOPG  4
#define TOPK  8
#define NE    33      // 32 routed + 1 shared
#define CAP   1024
#define RSCALE 2.5f

// GEMM tiling
#define BK    64                 // fp32 k-chunk
#define STR   72                 // padded fp16 row stride (144B -> conflict-free ldmatrix)
#define TILEB (128 * STR * 2)    // bytes per 128xBK fp16 tile = 18432
#define BUFB  (3 * TILEB)        // Ahi, Alo, B = 55296
#define SMEMB (2 * BUFB)         // double buffer = 110592

// ---------------- static scratch (no allocations allowed) ----------------
__device__ float g_combine[T_TOK * NEXP];
__device__ int   g_count[NE];
__device__ int   g_token[NE * CAP];
__device__ float g_wt[NE * CAP];
__device__ int   g_rowid[NEXP * T_TOK];                    // [e][t] -> row or -1
__device__ float g_act[(size_t)NE * CAP * IDIM];           // silu(g)*u rows
__device__ float g_down[(size_t)NE * CAP * HID];           // weighted down-proj rows

__device__ __forceinline__ float silu_f(float v) {
    return v / (1.0f + expf(-v));
}

__device__ __forceinline__ uint32_t smem_u32(const void* p) {
    uint32_t a;
    asm("{ .reg .u64 t; cvta.to.shared.u64 t, %1; cvt.u32.u64 %0, t; }"
        : "=r"(a) : "l"(p));
    return a;
}

__device__ __forceinline__ void ldm4(uint32_t* r, uint32_t addr) {
    asm volatile("ldmatrix.sync.aligned.m8n8.x4.shared.b16 {%0,%1,%2,%3}, [%4];"
        : "=r"(r[0]), "=r"(r[1]), "=r"(r[2]), "=r"(r[3]) : "r"(addr));
}
__device__ __forceinline__ void mma16816h(float* c, const uint32_t* a, const uint32_t* b) {
    asm volatile("mma.sync.aligned.m16n8k16.row.col.f32.f16.f16.f32 "
        "{%0,%1,%2,%3}, {%4,%5,%6,%7}, {%8,%9}, {%0,%1,%2,%3};"
        : "+f"(c[0]), "+f"(c[1]), "+f"(c[2]), "+f"(c[3])
        : "r"(a[0]), "r"(a[1]), "r"(a[2]), "r"(a[3]), "r"(b[0]), "r"(b[1]));
}

// split fp32x4 -> fp16 hi + fp16 lo, store 8B each
__device__ __forceinline__ void split_store_h(uint32_t ahi, uint32_t alo, float4 v) {
    __half h0 = __float2half_rn(v.x), h1 = __float2half_rn(v.y);
    __half h2 = __float2half_rn(v.z), h3 = __float2half_rn(v.w);
    __half l0 = __float2half_rn(v.x - __half2float(h0));
    __half l1 = __float2half_rn(v.y - __half2float(h1));
    __half l2 = __float2half_rn(v.z - __half2float(h2));
    __half l3 = __float2half_rn(v.w - __half2float(h3));
    unsigned long long H =
        (unsigned long long)__half_as_ushort(h0) |
        ((unsigned long long)__half_as_ushort(h1) << 16) |
        ((unsigned long long)__half_as_ushort(h2) << 32) |
        ((unsigned long long)__half_as_ushort(h3) << 48);
    unsigned long long L =
        (unsigned long long)__half_as_ushort(l0) |
        ((unsigned long long)__half_as_ushort(l1) << 16) |
        ((unsigned long long)__half_as_ushort(l2) << 32) |
        ((unsigned long long)__half_as_ushort(l3) << 48);
    asm volatile("st.shared.b64 [%0], %1;" :: "r"(ahi), "l"(H) : "memory");
    asm volatile("st.shared.b64 [%0], %1;" :: "r"(alo), "l"(L) : "memory");
}

// fp32x4 -> fp16 single, store 8B
__device__ __forceinline__ void store_h(uint32_t a, float4 v) {
    __half h0 = __float2half_rn(v.x), h1 = __float2half_rn(v.y);
    __half h2 = __float2half_rn(v.z), h3 = __float2half_rn(v.w);
    unsigned long long H =
        (unsigned long long)__half_as_ushort(h0) |
        ((unsigned long long)__half_as_ushort(h1) << 16) |
        ((unsigned long long)__half_as_ushort(h2) << 32) |
        ((unsigned long long)__half_as_ushort(h3) << 48);
    asm volatile("st.shared.b64 [%0], %1;" :: "r"(a), "l"(H) : "memory");
}

// ---------------- 1) router ----------------
__global__ void router_kernel(const float* __restrict__ x,
                              const float* __restrict__ gw,
                              const float* __restrict__ bias) {
    __shared__ float sx[HID];
    __shared__ float slog[NEXP];
    int t = blockIdx.x;
    const float* xr = x + (size_t)t * HID;
    for (int k = threadIdx.x; k < HID; k += blockDim.x) sx[k] = xr[k];
    __syncthreads();
    int warp = threadIdx.x >> 5, lane = threadIdx.x & 31;
    for (int e = warp; e < NEXP; e += 8) {
        const float* w = gw + (size_t)e * HID;
        float acc = 0.f;
        for (int k = lane; k < HID; k += 32) acc = fmaf(sx[k], w[k], acc);
        #pragma unroll
        for (int o = 16; o; o >>= 1) acc += __shfl_down_sync(0xffffffffu, acc, o);
        if (lane == 0) slog[e] = acc;
    }
    __syncthreads();
    if (threadIdx.x == 0) {
        float s[NEXP], sr[NEXP];
        #pragma unroll
        for (int e = 0; e < NEXP; e++) {
            float sc = 1.f / (1.f + expf(-slog[e]));
            s[e] = sc;
            sr[e] = sc + bias[e];
        }
        float gs[NGRP];
        #pragma unroll
        for (int g = 0; g < NGRP; g++) {
            float m1 = -1e30f, m2 = -1e30f;
            #pragma unroll
            for (int j = 0; j < EPG; j++) {
                float v = sr[g * EPG + j];
                if (v > m1) { m2 = m1; m1 = v; }
                else if (v > m2) { m2 = v; }
            }
            gs[g] = m1 + m2;
        }
        bool gsel[NGRP];
        #pragma unroll
        for (int g = 0; g < NGRP; g++) gsel[g] = false;
        for (int it = 0; it < TOPG; it++) {
            float best = -1e30f; int bi = 0;
            for (int g = 0; g < NGRP; g++)
                if (!gsel[g] && gs[g] > best) { best = gs[g]; bi = g; }
            gsel[bi] = true;
        }
        bool taken[NEXP];
        #pragma unroll
        for (int e = 0; e < NEXP; e++) taken[e] = false;
        int ids[TOPK];
        for (int it = 0; it < TOPK; it++) {
            float best = -1e30f; int bi = 0;
            for (int e = 0; e < NEXP; e++)
                if (gsel[e >> 2] && !taken[e] && sr[e] > best) { best = sr[e]; bi = e; }
            taken[bi] = true;
            ids[it] = bi;
        }
        float sum = 0.f;
        for (int k = 0; k < TOPK; k++) sum += s[ids[k]];
        float inv = RSCALE / (sum + 1e-20f);
        float out[NEXP];
        #pragma unroll
        for (int e = 0; e < NEXP; e++) out[e] = 0.f;
        for (int k = 0; k < TOPK; k++) out[ids[k]] = s[ids[k]] * inv;
        #pragma unroll
        for (int e = 0; e < NEXP; e++) g_combine[t * NEXP + e] = out[e];
    }
}

// ---------------- 2) compact per-expert token lists ----------------
__global__ void build_lists_kernel() {
    int e = blockIdx.x;
    int t = threadIdx.x;
    __shared__ int sc[T_TOK];
    float w;
    int flag;
    if (e < NEXP) {
        w = g_combine[t * NEXP + e];
        flag = (w > 0.f) ? 1 : 0;
    } else {
        w = 1.0f;
        flag = 1;
    }
    sc[t] = flag;
    __syncthreads();
    for (int off = 1; off < T_TOK; off <<= 1) {
        int v = (t >= off) ? sc[t - off] : 0;
        __syncthreads();
        sc[t] += v;
        __syncthreads();
    }
    int pos = sc[t] - flag;
    if (flag) {
        g_token[e * CAP + pos] = t;
        g_wt[e * CAP + pos] = w;
    }
    if (e < NEXP) g_rowid[e * T_TOK + t] = flag ? (e * CAP + pos) : -1;
    if (t == T_TOK - 1) g_count[e] = sc[T_TOK - 1];
}

// ---------------- 3) gate_up GEMM via fp16 mma.sync (A hi/lo split, 2 terms)
// CTA tile: M=128 rows, D = 128 cols interleaved (even=gate j, odd=up j).
// 512 threads = 16 warps of 32x32; BK=64, double buffered.
__global__ void __launch_bounds__(512, 1)
gateup_mma(const float* __restrict__ x,
           const float* __restrict__ wgu,
           const float* __restrict__ sgu) {
    int e = blockIdx.z;
    int cnt = g_count[e];
    int m0 = blockIdx.x * 128;
    if (m0 >= cnt) return;
    int n0 = blockIdx.y * 64;
    const float* W = (e < NEXP) ? (wgu + (size_t)e * (2 * IDIM) * HID) : sgu;

    extern __shared__ char smem[];
    uint32_t sb = smem_u32(smem);
    int tid = threadIdx.x;
    int lane = tid & 31, wid = tid >> 5;

    // loader: 4 threads per tile row, each covers 16 floats of the 64-float chunk
    int lrow = tid >> 2, lquad = tid & 3;
    int mrow = m0 + lrow; if (mrow > cnt - 1) mrow = cnt - 1;
    const float* aptr = x + (size_t)g_token[e * CAP + mrow] * HID + lquad * 16;
    int jcol = lrow >> 1;
    int wrow = (lrow & 1) ? (IDIM + n0 + jcol) : (n0 + jcol);
    const float* bptr = W + (size_t)wrow * HID + lquad * 16;
    uint32_t soff = (uint32_t)(lrow * STR + lquad * 16) * 2;

    // warp grid 4x4: each warp 32 rows x 32 cols
    int wm0 = (wid >> 2) * 32, wn0 = (wid & 3) * 32;
    uint32_t a_r = (uint32_t)(wm0 + (lane & 15));
    uint32_t a_c8 = (uint32_t)((lane >> 4) * 8);
    uint32_t b_row = (uint32_t)((lane & 7) + ((lane >> 4) << 3));
    uint32_t b_k8 = (uint32_t)(((lane >> 3) & 1) * 8);

    float acc[2][4][4];
    #pragma unroll
    for (int mi = 0; mi < 2; mi++)
        #pragma unroll
        for (int ni = 0; ni < 4; ni++)
            #pragma unroll
            for (int q = 0; q < 4; q++) acc[mi][ni][q] = 0.f;

    float4 ra[4], rb[4];
    #pragma unroll
    for (int q = 0; q < 4; q++) {
        ra[q] = *(const float4*)(aptr + q * 4);
        rb[q] = *(const float4*)(bptr + q * 4);
    }
    #pragma unroll
    for (int q = 0; q < 4; q++) {
        uint32_t o = soff + q * 8;
        split_store_h(sb + o, sb + TILEB + o, ra[q]);
        store_h(sb + 2 * TILEB + o, rb[q]);
    }
    __syncthreads();

    const int NC = HID / BK;  // 32
    for (int c = 0; c < NC; c++) {
        if (c + 1 < NC) {
            const float* ap = aptr + (c + 1) * BK;
            const float* bp = bptr + (c + 1) * BK;
            #pragma unroll
            for (int q = 0; q < 4; q++) {
                ra[q] = *(const float4*)(ap + q * 4);
                rb[q] = *(const float4*)(bp + q * 4);
            }
        }
        uint32_t cur = sb + (uint32_t)(c & 1) * BUFB;
        #pragma unroll
        for (int kh = 0; kh < 4; kh++) {
            uint32_t ah[2][4], al[2][4], bh[2][4];
            #pragma unroll
            for (int mi = 0; mi < 2; mi++) {
                uint32_t ad = cur + ((a_r + mi * 16) * STR + kh * 16 + a_c8) * 2;
                ldm4(ah[mi], ad);
                ldm4(al[mi], ad + TILEB);
            }
            #pragma unroll
            for (int nj = 0; nj < 2; nj++) {
                uint32_t bd = cur + 2 * TILEB +
                    ((wn0 + nj * 16 + b_row) * STR + kh * 16 + b_k8) * 2;
                ldm4(bh[nj], bd);
            }
            #pragma unroll
            for (int mi = 0; mi < 2; mi++)
                #pragma unroll
                for (int ni = 0; ni < 4; ni++) {
                    const uint32_t* bhp = &bh[ni >> 1][(ni & 1) * 2];
                    mma16816h(acc[mi][ni], ah[mi], bhp);
                    mma16816h(acc[mi][ni], al[mi], bhp);
                }
        }
        if (c + 1 < NC) {
            uint32_t nb = sb + (uint32_t)((c + 1) & 1) * BUFB;
            #pragma unroll
            for (int q = 0; q < 4; q++) {
                uint32_t o = soff + q * 8;
                split_store_h(nb + o, nb + TILEB + o, ra[q]);
                store_h(nb + 2 * TILEB + o, rb[q]);
            }
        }
        __syncthreads();
    }

    // epilogue: c0=gate, c1=up for col j; rows g and g+8
    int g = lane >> 2, tc = (lane & 3) * 2;
    #pragma unroll
    for (int mi = 0; mi < 2; mi++) {
        int r0 = m0 + wm0 + mi * 16 + g;
        int r1 = r0 + 8;
        #pragma unroll
        for (int ni = 0; ni < 4; ni++) {
            int col = n0 + ((wn0 + ni * 8 + tc) >> 1);
            if (r0 < cnt)
                g_act[((size_t)e * CAP + r0) * IDIM + col] =
                    silu_f(acc[mi][ni][0]) * acc[mi][ni][1];
            if (r1 < cnt)
                g_act[((size_t)e * CAP + r1) * IDIM + col] =
                    silu_f(acc[mi][ni][2]) * acc[mi][ni][3];
        }
    }
}

// ---------------- 4) down GEMM via fp16 mma.sync (2 terms), weighted --------
__global__ void __launch_bounds__(512, 1)
down_mma(const float* __restrict__ wdn,
         const float* __restrict__ sdn) {
    int e = blockIdx.z;
    int cnt = g_count[e];
    int m0 = blockIdx.x * 128;
    if (m0 >= cnt) return;
    int n0 = blockIdx.y * 128;
    const float* W = (e < NEXP) ? (wdn + (size_t)e * HID * IDIM) : sdn;

    extern __shared__ char smem[];
    uint32_t sb = smem_u32(smem);
    int tid = threadIdx.x;
    int lane = tid & 31, wid = tid >> 5;

    int lrow = tid >> 2, lquad = tid & 3;
    int mrow = m0 + lrow; if (mrow > cnt - 1) mrow = cnt - 1;
    const float* aptr = g_act + ((size_t)e * CAP + mrow) * IDIM + lquad * 16;
    const float* bptr = W + (size_t)(n0 + lrow) * IDIM + lquad * 16;
    uint32_t soff = (uint32_t)(lrow * STR + lquad * 16) * 2;

    int wm0 = (wid >> 2) * 32, wn0 = (wid & 3) * 32;
    uint32_t a_r = (uint32_t)(wm0 + (lane & 15));
    uint32_t a_c8 = (uint32_t)((lane >> 4) * 8);
    uint32_t b_row = (uint32_t)((lane & 7) + ((lane >> 4) << 3));
    uint32_t b_k8 = (uint32_t)(((lane >> 3) & 1) * 8);

    float acc[2][4][4];
    #pragma unroll
    for (int mi = 0; mi < 2; mi++)
        #pragma unroll
        for (int ni = 0; ni < 4; ni++)
            #pragma unroll
            for (int q = 0; q < 4; q++) acc[mi][ni][q] = 0.f;

    float4 ra[4], rb[4];
    #pragma unroll
    for (int q = 0; q < 4; q++) {
        ra[q] = *(const float4*)(aptr + q * 4);
        rb[q] = *(const float4*)(bptr + q * 4);
    }
    #pragma unroll
    for (int q = 0; q < 4; q++) {
        uint32_t o = soff + q * 8;
        split_store_h(sb + o, sb + TILEB + o, ra[q]);
        store_h(sb + 2 * TILEB + o, rb[q]);
    }
    __syncthreads();

    const int NC = IDIM / BK;  // 16
    for (int c = 0; c < NC; c++) {
        if (c + 1 < NC) {
            const float* ap = aptr + (c + 1) * BK;
            const float* bp = bptr + (c + 1) * BK;
            #pragma unroll
            for (int q = 0; q < 4; q++) {
                ra[q] = *(const float4*)(ap + q * 4);
                rb[q] = *(const float4*)(bp + q * 4);
            }
        }
        uint32_t cur = sb + (uint32_t)(c & 1) * BUFB;
        #pragma unroll
        for (int kh = 0; kh < 4; kh++) {
            uint32_t ah[2][4], al[2][4], bh[2][4];
            #pragma unroll
            for (int mi = 0; mi < 2; mi++) {
                uint32_t ad = cur + ((a_r + mi * 16) * STR + kh * 16 + a_c8) * 2;
                ldm4(ah[mi], ad);
                ldm4(al[mi], ad + TILEB);
            }
            #pragma unroll
            for (int nj = 0; nj < 2; nj++) {
                uint32_t bd = cur + 2 * TILEB +
                    ((wn0 + nj * 16 + b_row) * STR + kh * 16 + b_k8) * 2;
                ldm4(bh[nj], bd);
            }
            #pragma unroll
            for (int mi = 0; mi < 2; mi++)
                #pragma unroll
                for (int ni = 0; ni < 4; ni++) {
                    const uint32_t* bhp = &bh[ni >> 1][(ni & 1) * 2];
                    mma16816h(acc[mi][ni], ah[mi], bhp);
                    mma16816h(acc[mi][ni], al[mi], bhp);
                }
        }
        if (c + 1 < NC) {
            uint32_t nb = sb + (uint32_t)((c + 1) & 1) * BUFB;
            #pragma unroll
            for (int q = 0; q < 4; q++) {
                uint32_t o = soff + q * 8;
                split_store_h(nb + o, nb + TILEB + o, ra[q]);
                store_h(nb + 2 * TILEB + o, rb[q]);
            }
        }
        __syncthreads();
    }

    int g = lane >> 2, tc = (lane & 3) * 2;
    #pragma unroll
    for (int mi = 0; mi < 2; mi++) {
        int r0 = m0 + wm0 + mi * 16 + g;
        int r1 = r0 + 8;
        float w0 = (r0 < cnt) ? g_wt[e * CAP + r0] : 0.f;
        float w1 = (r1 < cnt) ? g_wt[e * CAP + r1] : 0.f;
        #pragma unroll
        for (int ni = 0; ni < 4; ni++) {
            int col = n0 + wn0 + ni * 8 + tc;
            if (r0 < cnt) {
                float2 v = make_float2(acc[mi][ni][0] * w0, acc[mi][ni][1] * w0);
                *(float2*)(g_down + ((size_t)e * CAP + r0) * HID + col) = v;
            }
            if (r1 < cnt) {
                float2 v = make_float2(acc[mi][ni][2] * w1, acc[mi][ni][3] * w1);
                *(float2*)(g_down + ((size_t)e * CAP + r1) * HID + col) = v;
            }
        }
    }
}

// ---------------- 5) deterministic per-token combine ----------------
__global__ void combine_kernel(float* __restrict__ y) {
    int t = blockIdx.x;
    __shared__ int rows[NEXP];
    if (threadIdx.x < NEXP) rows[threadIdx.x] = g_rowid[threadIdx.x * T_TOK + t];
    __syncthreads();
    int h0 = threadIdx.x * 8;
    const float* sh = g_down + ((size_t)NEXP * CAP + t) * HID + h0;
    float4 s0 = *(const float4*)sh;
    float4 s1 = *(const float4*)(sh + 4);
    for (int e = 0; e < NEXP; e++) {
        int r = rows[e];
        if (r >= 0) {
            const float* p = g_down + (size_t)r * HID + h0;
            float4 a = *(const float4*)p;
            float4 b = *(const float4*)(p + 4);
            s0.x += a.x; s0.y += a.y; s0.z += a.z; s0.w += a.w;
            s1.x += b.x; s1.y += b.y; s1.z += b.z; s1.w += b.w;
        }
    }
    float* out = y + (size_t)t * HID + h0;
    *(float4*)out = s0;
    *(float4*)(out + 4) = s1;
}

// ---------------- launcher ----------------
extern "C" void kernel_launch(void* const* d_in, const int* in_sizes, int n_in,
                              void* d_out, int out_size) {
    const float* x    = (const float*)d_in[0];
    const float* gw   = (const float*)d_in[1];
    const float* bias = (const float*)d_in[2];
    const float* wgu  = (const float*)d_in[3];
    const float* wdn  = (const float*)d_in[4];
    const float* sgu  = (const float*)d_in[5];
    const float* sdn  = (const float*)d_in[6];
    float* y = (float*)d_out;

    cudaFuncSetAttribute(gateup_mma, cudaFuncAttributeMaxDynamicSharedMemorySize, SMEMB);
    cudaFuncSetAttribute(down_mma, cudaFuncAttributeMaxDynamicSharedMemorySize, SMEMB);

    router_kernel<<<T_TOK, 256>>>(x, gw, bias);
    build_lists_kernel<<<NE, T_TOK>>>();
    dim3 ga(CAP / 128, IDIM / 64, NE);
    gateup_mma<<<ga, 512, SMEMB>>>(x, wgu, sgu);
    dim3 gd(CAP / 128, HID / 128, NE);
    down_mma<<<gd, 512, SMEMB>>>(wdn, sdn);
    combine_kernel<<<T_TOK, 256>>>(y);
}